// round 14
// baseline (speedup 1.0000x reference)
#include <cuda_runtime.h>
#include <cuda_fp16.h>
#include <cstdint>
#include <math.h>

#define T_TOKENS 8192
#define D        4096
#define NS       4
#define HID      1024
#define NW       24
#define KT       128
#define TOKB     32
#define TAU_INV  20.0f
#define EPS_W    1e-6f

// ================= scratch =================
__device__ __half g_xhi[T_TOKENS * HID];
__device__ __half g_wh[HID * HID];
__device__ float g_wg[NW * D];
__device__ float g_Hpost[T_TOKENS * NS];
__device__ float g_Hres[T_TOKENS * NS * NS];

// ================= helpers =================
__device__ __forceinline__ uint32_t smem_to_u32(const void* p) {
    uint32_t a;
    asm("{ .reg .u64 t; cvta.to.shared.u64 t, %1; cvt.u32.u64 %0, t; }" : "=r"(a) : "l"(p));
    return a;
}
__device__ __forceinline__ void cp16(uint32_t s, const void* g) {
    asm volatile("cp.async.cg.shared.global [%0], [%1], 16;" :: "r"(s), "l"(g));
}
__device__ __forceinline__ void ldsm_x4(uint32_t& r0, uint32_t& r1, uint32_t& r2,
                                        uint32_t& r3, uint32_t addr) {
    asm volatile("ldmatrix.sync.aligned.m8n8.x4.shared.b16 {%0,%1,%2,%3}, [%4];"
                 : "=r"(r0), "=r"(r1), "=r"(r2), "=r"(r3) : "r"(addr));
}
__device__ __forceinline__ void mma16816h(float* c, const uint32_t* a, const uint32_t* b) {
    asm volatile(
        "mma.sync.aligned.m16n8k16.row.col.f32.f16.f16.f32 "
        "{%0,%1,%2,%3}, {%4,%5,%6,%7}, {%8,%9}, {%0,%1,%2,%3};"
        : "+f"(c[0]), "+f"(c[1]), "+f"(c[2]), "+f"(c[3])
        : "r"(a[0]), "r"(a[1]), "r"(a[2]), "r"(a[3]), "r"(b[0]), "r"(b[1]));
}
#define SW64(off) ((off) ^ (((off) >> 3) & 0x30))

__device__ __forceinline__ float lse4(float a0, float a1, float a2, float a3) {
    float m = fmaxf(fmaxf(a0, a1), fmaxf(a2, a3));
    float s = __expf(a0 - m) + __expf(a1 - m) + __expf(a2 - m) + __expf(a3 - m);
    return m + __logf(s);
}
__device__ __forceinline__ uint32_t packh2(__half a, __half b) {
    __half2 t = __halves2half2(a, b);
    return *(uint32_t*)&t;
}

// ============================================================
// Kernel 0: prep — fold rmsw into gate weights + W_sub -> fp16
// ============================================================
__global__ __launch_bounds__(256)
void prep_kernel(const float* __restrict__ Wpre, const float* __restrict__ Wpost,
                 const float* __restrict__ Wres, const float* __restrict__ rmsw,
                 const float* __restrict__ Wsub)
{
    int bid = blockIdx.x;
    if (bid < 384) {
        int idx = bid * 256 + threadIdx.x;
        int m = idx >> 12, k = idx & 4095;
        const float* Wr = (m < 4) ? (Wpre + m * D)
                         : (m < 8) ? (Wpost + (m - 4) * D)
                                   : (Wres + (m - 8) * D);
        g_wg[idx] = Wr[k] * rmsw[k];
    } else {
        int i = (bid - 384) * 256 + threadIdx.x;
        float4 v = ((const float4*)Wsub)[i];
        uint2 hv;
        hv.x = packh2(__float2half_rn(v.x), __float2half_rn(v.y));
        hv.y = packh2(__float2half_rn(v.z), __float2half_rn(v.w));
        ((uint2*)g_wh)[i] = hv;
    }
}

// ============================================================
// Kernel 1: gates + sinkhorn + x_layer (fp16 out)
//   TOKB=32: warp = 4 tokens x (3m x 4ks) lanes; W reused 4x.
// smem: stage s at s*29056: w[24][132]f (12672B) + x[32][128]f (16384B)
//   87168: s_dots[32][24]  90240: s_inv[32]  90368: s_hpre[32][4]
// ============================================================
#define G_STAGE    29056
#define G_XOFF     12672
#define GATES_SMEM 90880

__device__ __forceinline__ void gates_load_stage(
    uint32_t sst, int tid, const float* __restrict__ wg,
    const float* __restrict__ x, long t0, int k0)
{
    #pragma unroll
    for (int j = 0; j < 3; j++) {
        int idx = tid + j * 256;           // 24 rows x 32 chunks
        int m = idx >> 5, c = idx & 31;
        cp16(sst + m * 528 + c * 16, wg + m * D + k0 + c * 4);
    }
    #pragma unroll
    for (int j = 0; j < 4; j++) {
        int idx = tid + j * 256;           // 32 tokens x 32 chunks
        int tok = idx >> 5, c = idx & 31;
        cp16(sst + G_XOFF + tok * 512 + c * 16, x + (t0 + tok) * (long)D + k0 + c * 4);
    }
}

__global__ __launch_bounds__(256, 2)
void gates_kernel(const float* __restrict__ x,
                  const float* __restrict__ bpre,
                  const float* __restrict__ bpost,
                  const float* __restrict__ bres,
                  const float* __restrict__ apre,
                  const float* __restrict__ apost,
                  const float* __restrict__ ares)
{
    extern __shared__ __align__(16) char gsm[];
    const uint32_t sbase = smem_to_u32(gsm);
    float* s_dots = (float*)(gsm + 87168);   // [32][24]
    float* s_inv  = (float*)(gsm + 90240);   // [32]
    float* s_hpre = (float*)(gsm + 90368);   // [32][4]

    const int tid  = threadIdx.x;
    const int lane = tid & 31;
    const long t0  = (long)blockIdx.x * TOKB;

    const int ks = tid & 3;            // k quarter
    const int mt = (tid >> 2) & 7;     // m triple
    const int tp = tid >> 5;           // warp: tokens 4tp..4tp+3

    float acc[4][3];
    #pragma unroll
    for (int i = 0; i < 4; i++)
        #pragma unroll
        for (int j = 0; j < 3; j++) acc[i][j] = 0.f;
    float ss[4] = {0.f, 0.f, 0.f, 0.f};

    const float* wg = g_wg;

    gates_load_stage(sbase, tid, wg, x, t0, 0);
    asm volatile("cp.async.commit_group;" ::: "memory");
    gates_load_stage(sbase + G_STAGE, tid, wg, x, t0, KT);
    asm volatile("cp.async.commit_group;" ::: "memory");

    const int NIT = D / KT;   // 32
    for (int kt = 0; kt < NIT; kt++) {
        const int s = kt % 3;
        if (kt < NIT - 1) asm volatile("cp.async.wait_group 1;" ::: "memory");
        else              asm volatile("cp.async.wait_group 0;" ::: "memory");
        __syncthreads();
        if (kt + 2 < NIT) {
            gates_load_stage(sbase + ((kt + 2) % 3) * G_STAGE, tid, wg, x, t0,
                             (kt + 2) * KT);
            asm volatile("cp.async.commit_group;" ::: "memory");
        }

        const float4* sw = (const float4*)(gsm + s * G_STAGE);
        const float4* sx = (const float4*)(gsm + s * G_STAGE + G_XOFF) + (4 * tp) * 32;
        #pragma unroll
        for (int kk = 0; kk < 8; kk++) {
            int k4 = ks * 8 + ((kk + 2 * ks) & 7);
            float4 xv[4];
            xv[0] = sx[k4];
            xv[1] = sx[32 + k4];
            xv[2] = sx[64 + k4];
            xv[3] = sx[96 + k4];
            #pragma unroll
            for (int i = 0; i < 4; i++)
                ss[i] = fmaf(xv[i].x, xv[i].x, fmaf(xv[i].y, xv[i].y,
                         fmaf(xv[i].z, xv[i].z, fmaf(xv[i].w, xv[i].w, ss[i]))));
            #pragma unroll
            for (int j = 0; j < 3; j++) {
                float4 w = sw[(3 * mt + j) * 33 + k4];
                #pragma unroll
                for (int i = 0; i < 4; i++)
                    acc[i][j] = fmaf(xv[i].x, w.x, fmaf(xv[i].y, w.y,
                                 fmaf(xv[i].z, w.z, fmaf(xv[i].w, w.w, acc[i][j]))));
            }
        }
    }

    // sumsq: full-warp reduce; each k counted 8x by mt lanes -> x0.125
    #pragma unroll
    for (int i = 0; i < 4; i++) {
        float a = ss[i];
        #pragma unroll
        for (int o = 16; o; o >>= 1) a += __shfl_xor_sync(0xffffffffu, a, o);
        ss[i] = a;
    }
    // k-split reduce over ks (lane bits 0-1)
    #pragma unroll
    for (int i = 0; i < 4; i++)
        #pragma unroll
        for (int j = 0; j < 3; j++) {
            float a = acc[i][j];
            a += __shfl_xor_sync(0xffffffffu, a, 1);
            a += __shfl_xor_sync(0xffffffffu, a, 2);
            acc[i][j] = a;
        }
    __syncthreads();
    if (lane == 0) {
        #pragma unroll
        for (int i = 0; i < 4; i++)
            s_inv[4 * tp + i] = rsqrtf(ss[i] * (0.125f / D) + 1e-8f);
    }
    if (ks == 0) {
        #pragma unroll
        for (int i = 0; i < 4; i++)
            #pragma unroll
            for (int j = 0; j < 3; j++)
                s_dots[(4 * tp + i) * NW + 3 * mt + j] = acc[i][j];
    }
    __syncthreads();

    // ---- gate math: 4 warps, 4 lanes per token (32 tokens) ----
    if (tid < 128) {
        const int w4 = tid >> 5;
        const int tt = w4 * 8 + (lane >> 2), r = lane & 3;
        const int base = lane & ~3;
        const long t = t0 + tt;
        const float inv = s_inv[tt];
        const float* dt = s_dots + tt * NW;
        const float a_pre = apre[0], a_post = apost[0], a_res = ares[0];

        float zp = fmaf(a_pre, inv * dt[r], bpre[r]);
        float hp = 1.0f / (1.0f + __expf(-zp));
        float sp = hp;
        sp += __shfl_xor_sync(0xffffffffu, sp, 1);
        sp += __shfl_xor_sync(0xffffffffu, sp, 2);
        s_hpre[tt * 4 + r] = hp / (sp + EPS_W);

        float zq = fmaf(a_post, inv * dt[4 + r], bpost[r]);
        float hq = 2.0f / (1.0f + __expf(-zq));
        float sq = hq;
        sq += __shfl_xor_sync(0xffffffffu, sq, 1);
        sq += __shfl_xor_sync(0xffffffffu, sq, 2);
        g_Hpost[t * NS + r] = hq / (sq + EPS_W);

        float Zrow[4], Zcol[4];
        #pragma unroll
        for (int i = 0; i < 4; i++) {
            Zrow[i] = fmaf(a_res, inv * dt[8 + r * 4 + i], bres[r * 4 + i]) * TAU_INV;
            Zcol[i] = fmaf(a_res, inv * dt[8 + i * 4 + r], bres[i * 4 + r]) * TAU_INV;
        }
        float ur = 0.f, vr = 0.f;
        for (int it = 0; it < 20; it++) {
            float v0 = __shfl_sync(0xffffffffu, vr, base + 0);
            float v1 = __shfl_sync(0xffffffffu, vr, base + 1);
            float v2 = __shfl_sync(0xffffffffu, vr, base + 2);
            float v3 = __shfl_sync(0xffffffffu, vr, base + 3);
            ur = -lse4(Zrow[0] + v0, Zrow[1] + v1, Zrow[2] + v2, Zrow[3] + v3);
            float u0 = __shfl_sync(0xffffffffu, ur, base + 0);
            float u1 = __shfl_sync(0xffffffffu, ur, base + 1);
            float u2 = __shfl_sync(0xffffffffu, ur, base + 2);
            float u3 = __shfl_sync(0xffffffffu, ur, base + 3);
            vr = -lse4(Zcol[0] + u0, Zcol[1] + u1, Zcol[2] + u2, Zcol[3] + u3);
        }
        float v0 = __shfl_sync(0xffffffffu, vr, base + 0);
        float v1 = __shfl_sync(0xffffffffu, vr, base + 1);
        float v2 = __shfl_sync(0xffffffffu, vr, base + 2);
        float v3 = __shfl_sync(0xffffffffu, vr, base + 3);
        g_Hres[t * 16 + r * 4 + 0] = __expf(Zrow[0] + ur + v0);
        g_Hres[t * 16 + r * 4 + 1] = __expf(Zrow[1] + ur + v1);
        g_Hres[t * 16 + r * 4 + 2] = __expf(Zrow[2] + ur + v2);
        g_Hres[t * 16 + r * 4 + 3] = __expf(Zrow[3] + ur + v3);
    }
    __syncthreads();

    // ---- pass 3: x_layer -> fp16 ----
    #pragma unroll 4
    for (int gg = 0; gg < TOKB; gg++) {
        const long t = t0 + gg;
        const float h0 = s_hpre[gg * 4 + 0], h1 = s_hpre[gg * 4 + 1];
        const float h2 = s_hpre[gg * 4 + 2], h3 = s_hpre[gg * 4 + 3];
        const float4* xr = (const float4*)(x + t * D);
        float4 a = xr[tid], b = xr[256 + tid], c = xr[512 + tid], e = xr[768 + tid];
        float4 o;
        o.x = h0 * a.x + h1 * b.x + h2 * c.x + h3 * e.x;
        o.y = h0 * a.y + h1 * b.y + h2 * c.y + h3 * e.y;
        o.z = h0 * a.z + h1 * b.z + h2 * c.z + h3 * e.z;
        o.w = h0 * a.w + h1 * b.w + h2 * c.w + h3 * e.w;
        uint2 hv;
        hv.x = packh2(__float2half_rn(o.x), __float2half_rn(o.y));
        hv.y = packh2(__float2half_rn(o.z), __float2half_rn(o.w));
        ((uint2*)g_xhi)[t * 256 + tid] = hv;
    }
}

// ============================================================
// Kernel 2: fp16 1-term GEMM (mma.sync) + fused mix epilogue
//   CTA 128x128, 8 warps, GK=32/stage (16KB), 4 stages, 2 CTAs/SM.
// ============================================================
#define GM 128
#define GN 128
#define GK 32
#define ST_A 0
#define ST_B 8192
#define STAGE_BYTES 16384
#define NSTAGE 4
#define EP_YS   0
#define EP_HRES 69632
#define EP_HPST 77824
#define GEMM_SMEM 79872

__device__ __forceinline__ void load_stage(
    uint32_t sstage, int tid, int m0, int n0, int k0,
    const __half* __restrict__ Ah, const __half* __restrict__ Bh)
{
    #pragma unroll
    for (int j = 0; j < 4; j++) {
        int i = tid + (j << 8);
        int mat = i >> 9;
        int w = i & 511;
        int r = w >> 2, c = w & 3;
        uint32_t so = SW64((uint32_t)(r * 64 + c * 16));
        const __half* src = (mat == 0) ? Ah : Bh;
        size_t go = (mat == 0) ? ((size_t)(m0 + r) * HID + k0 + c * 8)
                               : ((size_t)(n0 + r) * HID + k0 + c * 8);
        cp16(sstage + mat * 8192 + so, src + go);
    }
}

__global__ __launch_bounds__(256, 2)
void gemm_tc_kernel(const __half* __restrict__ Ah,
                    const __half* __restrict__ Bh,
                    const float* __restrict__ x,
                    float* __restrict__ out)
{
    extern __shared__ __align__(16) char smem[];
    uint32_t sbase = smem_to_u32(smem);
    const int tid = threadIdx.x, wid = tid >> 5, lane = tid & 31;
    const int wm = wid & 3, wn = wid >> 2;
    const int m0 = blockIdx.y * GM, n0 = blockIdx.x * GN;

    float acc[2][8][4];
    #pragma unroll
    for (int h = 0; h < 2; h++)
        #pragma unroll
        for (int g = 0; g < 8; g++)
            #pragma unroll
            for (int q = 0; q < 4; q++) acc[h][g][q] = 0.f;

    const int a_row = (lane & 15);
    const int a_kx  = ((lane >> 4) & 1) * 16;
    const int b_row = (lane & 7) + ((lane >> 4) & 1) * 8;
    const int b_kx  = ((lane >> 3) & 1) * 16;

    #pragma unroll
    for (int p = 0; p < 3; p++) {
        load_stage(sbase + p * STAGE_BYTES, tid, m0, n0, p * GK, Ah, Bh);
        asm volatile("cp.async.commit_group;" ::: "memory");
    }

    const int NITER = HID / GK;   // 32
    for (int i = 0; i < NITER; i++) {
        if (i + 2 < NITER)      asm volatile("cp.async.wait_group 2;" ::: "memory");
        else if (i + 1 < NITER) asm volatile("cp.async.wait_group 1;" ::: "memory");
        else                    asm volatile("cp.async.wait_group 0;" ::: "memory");
        __syncthreads();
        if (i + 3 < NITER) {
            load_stage(sbase + ((i + 3) % NSTAGE) * STAGE_BYTES, tid, m0, n0,
                       (i + 3) * GK, Ah, Bh);
            asm volatile("cp.async.commit_group;" ::: "memory");
        }

        uint32_t stg = sbase + (i % NSTAGE) * STAGE_BYTES;
        #pragma unroll
        for (int kk = 0; kk < 2; kk++) {
            const int kb = kk * 32;
            uint32_t ah[2][4];
            #pragma unroll
            for (int h = 0; h < 2; h++) {
                uint32_t off = SW64((uint32_t)((32 * wm + 16 * h + a_row) * 64 + kb + a_kx));
                ldsm_x4(ah[h][0], ah[h][1], ah[h][2], ah[h][3], stg + ST_A + off);
            }
            #pragma unroll
            for (int g = 0; g < 4; g++) {
                uint32_t bh[4];
                uint32_t off = SW64((uint32_t)((64 * wn + 16 * g + b_row) * 64 + kb + b_kx));
                ldsm_x4(bh[0], bh[1], bh[2], bh[3], stg + ST_B + off);
                #pragma unroll
                for (int half = 0; half < 2; half++)
                    #pragma unroll
                    for (int h = 0; h < 2; h++)
                        mma16816h(acc[h][g * 2 + half], ah[h], &bh[2 * half]);
            }
        }
    }

    // ================== fused mix epilogue ==================
    __syncthreads();
    float* ys  = (float*)(smem + EP_YS);   // [128][132]
    float* shr = (float*)(smem + EP_HRES); // [128][16]
    float* shp = (float*)(smem + EP_HPST); // [128][4]

    {
        const int r0 = 32 * wm + (lane >> 2);
        const int c0 = 64 * wn + (lane & 3) * 2;
        #pragma unroll
        for (int h = 0; h < 2; h++)
            #pragma unroll
            for (int ng = 0; ng < 8; ng++) {
                int rr = r0 + 16 * h, cc = c0 + 8 * ng;
                *(float2*)&ys[rr * 132 + cc]       = make_float2(acc[h][ng][0], acc[h][ng][1]);
                *(float2*)&ys[(rr + 8) * 132 + cc] = make_float2(acc[h][ng][2], acc[h][ng][3]);
            }
    }
    #pragma unroll
    for (int j = 0; j < 8; j++) shr[tid + j * 256] = g_Hres[(size_t)m0 * 16 + tid + j * 256];
    #pragma unroll
    for (int j = 0; j < 2; j++) shp[tid + j * 256] = g_Hpost[(size_t)m0 * 4 + tid + j * 256];
    __syncthreads();

    const int col4 = lane;
    #pragma unroll 2
    for (int it = 0; it < 16; it++) {
        const int trow = wid + 8 * it;
        const size_t t = (size_t)(m0 + trow);
        const float* hr = shr + trow * 16;
        const float p0 = shp[trow * 4 + 0], p1 = shp[trow * 4 + 1];
        const float p2 = shp[trow * 4 + 2], p3 = shp[trow * 4 + 3];
        float4 y4 = *(const float4*)&ys[trow * 132 + col4 * 4];
        const float* xb = x + t * D + n0 + col4 * 4;
        float4 xi0 = *(const float4*)(xb);
        float4 xi1 = *(const float4*)(xb + 1024);
        float4 xi2 = *(const float4*)(xb + 2048);
        float4 xi3 = *(const float4*)(xb + 3072);
        float* ob = out + t * D + n0 + col4 * 4;
        #pragma unroll
        for (int o = 0; o < 4; o++) {
            const float h0 = hr[o * 4 + 0], h1 = hr[o * 4 + 1];
            const float h2 = hr[o * 4 + 2], h3 = hr[o * 4 + 3];
            const float p = (o == 0) ? p0 : (o == 1) ? p1 : (o == 2) ? p2 : p3;
            float4 r;
            r.x = h0 * xi0.x + h1 * xi1.x + h2 * xi2.x + h3 * xi3.x + p * y4.x;
            r.y = h0 * xi0.y + h1 * xi1.y + h2 * xi2.y + h3 * xi3.y + p * y4.y;
            r.z = h0 * xi0.z + h1 * xi1.z + h2 * xi2.z + h3 * xi3.z + p * y4.z;
            r.w = h0 * xi0.w + h1 * xi1.w + h2 * xi2.w + h3 * xi3.w + p * y4.w;
            *(float4*)(ob + o * 1024) = r;
        }
    }
}

// ============================================================
extern "C" void kernel_launch(void* const* d_in, const int* in_sizes, int n_in,
                              void* d_out, int out_size)
{
    const float* x      = (const float*)d_in[0];
    const float* rmsw   = (const float*)d_in[1];
    const float* Wpre   = (const float*)d_in[2];
    const float* Wpost  = (const float*)d_in[3];
    const float* Wres   = (const float*)d_in[4];
    const float* bpre   = (const float*)d_in[5];
    const float* bpost  = (const float*)d_in[6];
    const float* bres   = (const float*)d_in[7];
    const float* apre   = (const float*)d_in[8];
    const float* apost  = (const float*)d_in[9];
    const float* ares   = (const float*)d_in[10];
    const float* Wsub   = (const float*)d_in[11];
    float* out = (float*)d_out;

    __half *xhi_p, *wh_p;
    cudaGetSymbolAddress((void**)&xhi_p, g_xhi);
    cudaGetSymbolAddress((void**)&wh_p, g_wh);

    cudaFuncSetAttribute(gemm_tc_kernel,
                         cudaFuncAttributeMaxDynamicSharedMemorySize, GEMM_SMEM);
    cudaFuncSetAttribute(gates_kernel,
                         cudaFuncAttributeMaxDynamicSharedMemorySize, GATES_SMEM);

    prep_kernel<<<384 + HID * HID / 4 / 256, 256>>>(Wpre, Wpost, Wres, rmsw, Wsub);
    gates_kernel<<<T_TOKENS / TOKB, 256, GATES_SMEM>>>(x, bpre, bpost, bres,
                                                       apre, apost, ares);
    gemm_tc_kernel<<<dim3(HID / GN, T_TOKENS / GM), 256, GEMM_SMEM>>>(
        xhi_p, wh_p, x, out);
}

// round 15
// speedup vs baseline: 1.3496x; 1.3496x over previous
#include <cuda_runtime.h>
#include <cuda_fp16.h>
#include <cstdint>
#include <math.h>

#define T_TOKENS 8192
#define D        4096
#define NS       4
#define HID      1024
#define NW       24
#define KT       128
#define TOKB     16
#define TAU_INV  20.0f
#define EPS_W    1e-6f

// ================= scratch =================
__device__ __half g_xhi[T_TOKENS * HID];
__device__ __half g_wh[HID * HID];
__device__ float g_wg[NW * D];
__device__ float g_Hpost[T_TOKENS * NS];
__device__ float g_Hres[T_TOKENS * NS * NS];

// ================= helpers =================
__device__ __forceinline__ uint32_t smem_to_u32(const void* p) {
    uint32_t a;
    asm("{ .reg .u64 t; cvta.to.shared.u64 t, %1; cvt.u32.u64 %0, t; }" : "=r"(a) : "l"(p));
    return a;
}
__device__ __forceinline__ void cp16(uint32_t s, const void* g) {
    asm volatile("cp.async.cg.shared.global [%0], [%1], 16;" :: "r"(s), "l"(g));
}
__device__ __forceinline__ void ldsm_x4(uint32_t& r0, uint32_t& r1, uint32_t& r2,
                                        uint32_t& r3, uint32_t addr) {
    asm volatile("ldmatrix.sync.aligned.m8n8.x4.shared.b16 {%0,%1,%2,%3}, [%4];"
                 : "=r"(r0), "=r"(r1), "=r"(r2), "=r"(r3) : "r"(addr));
}
__device__ __forceinline__ void mma16816h(float* c, const uint32_t* a, const uint32_t* b) {
    asm volatile(
        "mma.sync.aligned.m16n8k16.row.col.f32.f16.f16.f32 "
        "{%0,%1,%2,%3}, {%4,%5,%6,%7}, {%8,%9}, {%0,%1,%2,%3};"
        : "+f"(c[0]), "+f"(c[1]), "+f"(c[2]), "+f"(c[3])
        : "r"(a[0]), "r"(a[1]), "r"(a[2]), "r"(a[3]), "r"(b[0]), "r"(b[1]));
}
#define SW64(off) ((off) ^ (((off) >> 3) & 0x30))

__device__ __forceinline__ float lse4(float a0, float a1, float a2, float a3) {
    float m = fmaxf(fmaxf(a0, a1), fmaxf(a2, a3));
    float s = __expf(a0 - m) + __expf(a1 - m) + __expf(a2 - m) + __expf(a3 - m);
    return m + __logf(s);
}
__device__ __forceinline__ uint32_t packh2(__half a, __half b) {
    __half2 t = __halves2half2(a, b);
    return *(uint32_t*)&t;
}

// ============================================================
// Kernel 0: prep — fold rmsw into gate weights + W_sub -> fp16
// ============================================================
__global__ __launch_bounds__(256)
void prep_kernel(const float* __restrict__ Wpre, const float* __restrict__ Wpost,
                 const float* __restrict__ Wres, const float* __restrict__ rmsw,
                 const float* __restrict__ Wsub)
{
    int bid = blockIdx.x;
    if (bid < 384) {
        int idx = bid * 256 + threadIdx.x;
        int m = idx >> 12, k = idx & 4095;
        const float* Wr = (m < 4) ? (Wpre + m * D)
                         : (m < 8) ? (Wpost + (m - 4) * D)
                                   : (Wres + (m - 8) * D);
        g_wg[idx] = Wr[k] * rmsw[k];
    } else {
        int i = (bid - 384) * 256 + threadIdx.x;
        float4 v = ((const float4*)Wsub)[i];
        uint2 hv;
        hv.x = packh2(__float2half_rn(v.x), __float2half_rn(v.y));
        hv.y = packh2(__float2half_rn(v.z), __float2half_rn(v.w));
        ((uint2*)g_wh)[i] = hv;
    }
}

// ============================================================
// Kernel 1: gates + sinkhorn + x_layer (fp16 out)
//   R13 structure, 2-stage pipeline -> 42.6KB smem -> occ 4.
// ============================================================
#define G_STAGE    20864
#define G_XOFF     12672
#define GD_DOTS    41728
#define GD_INV     43264
#define GD_HPRE    43328
#define GATES_SMEM 43584

__device__ __forceinline__ void gates_load_stage(
    uint32_t sst, int tid, const float* __restrict__ wg,
    const float* __restrict__ x, long t0, int k0)
{
    #pragma unroll
    for (int j = 0; j < 3; j++) {
        int idx = tid + j * 256;
        int m = idx >> 5, c = idx & 31;
        cp16(sst + m * 528 + c * 16, wg + m * D + k0 + c * 4);
    }
    #pragma unroll
    for (int j = 0; j < 2; j++) {
        int idx = tid + j * 256;
        int tok = idx >> 5, c = idx & 31;
        cp16(sst + G_XOFF + tok * 512 + c * 16, x + (t0 + tok) * (long)D + k0 + c * 4);
    }
}

__global__ __launch_bounds__(256, 4)
void gates_kernel(const float* __restrict__ x,
                  const float* __restrict__ bpre,
                  const float* __restrict__ bpost,
                  const float* __restrict__ bres,
                  const float* __restrict__ apre,
                  const float* __restrict__ apost,
                  const float* __restrict__ ares)
{
    extern __shared__ __align__(16) char gsm[];
    const uint32_t sbase = smem_to_u32(gsm);
    float* s_dots = (float*)(gsm + GD_DOTS);
    float* s_inv  = (float*)(gsm + GD_INV);
    float* s_hpre = (float*)(gsm + GD_HPRE);

    const int tid  = threadIdx.x;
    const int lane = tid & 31;
    const long t0  = (long)blockIdx.x * TOKB;

    const int ks = tid & 3;
    const int mt = (tid >> 2) & 7;
    const int tp = tid >> 5;

    float acc[2][3] = {{0.f,0.f,0.f},{0.f,0.f,0.f}};
    float ss0 = 0.f, ss1 = 0.f;

    const float* wg = g_wg;

    gates_load_stage(sbase, tid, wg, x, t0, 0);
    asm volatile("cp.async.commit_group;" ::: "memory");

    const int NIT = D / KT;   // 32
    for (int kt = 0; kt < NIT; kt++) {
        asm volatile("cp.async.wait_group 0;" ::: "memory");
        __syncthreads();
        if (kt + 1 < NIT) {
            gates_load_stage(sbase + ((kt + 1) & 1) * G_STAGE, tid, wg, x, t0,
                             (kt + 1) * KT);
            asm volatile("cp.async.commit_group;" ::: "memory");
        }

        const float4* sw  = (const float4*)(gsm + (kt & 1) * G_STAGE);
        const float4* x4a = (const float4*)(gsm + (kt & 1) * G_STAGE + G_XOFF) + (2 * tp) * 32;
        const float4* x4b = x4a + 32;
        #pragma unroll
        for (int kk = 0; kk < 8; kk++) {
            int k4 = ks * 8 + ((kk + 2 * ks) & 7);
            float4 xa = x4a[k4];
            float4 xb = x4b[k4];
            ss0 = fmaf(xa.x, xa.x, fmaf(xa.y, xa.y, fmaf(xa.z, xa.z, fmaf(xa.w, xa.w, ss0))));
            ss1 = fmaf(xb.x, xb.x, fmaf(xb.y, xb.y, fmaf(xb.z, xb.z, fmaf(xb.w, xb.w, ss1))));
            #pragma unroll
            for (int j = 0; j < 3; j++) {
                float4 w = sw[(3 * mt + j) * 33 + k4];
                acc[0][j] = fmaf(xa.x, w.x, fmaf(xa.y, w.y, fmaf(xa.z, w.z, fmaf(xa.w, w.w, acc[0][j]))));
                acc[1][j] = fmaf(xb.x, w.x, fmaf(xb.y, w.y, fmaf(xb.z, w.z, fmaf(xb.w, w.w, acc[1][j]))));
            }
        }
    }

    #pragma unroll
    for (int o = 16; o; o >>= 1) {
        ss0 += __shfl_xor_sync(0xffffffffu, ss0, o);
        ss1 += __shfl_xor_sync(0xffffffffu, ss1, o);
    }
    #pragma unroll
    for (int i = 0; i < 2; i++)
        #pragma unroll
        for (int j = 0; j < 3; j++) {
            float a = acc[i][j];
            a += __shfl_xor_sync(0xffffffffu, a, 1);
            a += __shfl_xor_sync(0xffffffffu, a, 2);
            acc[i][j] = a;
        }
    __syncthreads();
    if (lane == 0) {
        s_inv[2 * tp]     = rsqrtf(ss0 * (0.125f / D) + 1e-8f);
        s_inv[2 * tp + 1] = rsqrtf(ss1 * (0.125f / D) + 1e-8f);
    }
    if (ks == 0) {
        #pragma unroll
        for (int i = 0; i < 2; i++)
            #pragma unroll
            for (int j = 0; j < 3; j++)
                s_dots[(2 * tp + i) * NW + 3 * mt + j] = acc[i][j];
    }
    __syncthreads();

    if (tid < 64) {
        const int w2 = tid >> 5;
        const int tt = w2 * 8 + (lane >> 2), r = lane & 3;
        const int base = lane & ~3;
        const long t = t0 + tt;
        const float inv = s_inv[tt];
        const float* dt = s_dots + tt * NW;
        const float a_pre = apre[0], a_post = apost[0], a_res = ares[0];

        float zp = fmaf(a_pre, inv * dt[r], bpre[r]);
        float hp = 1.0f / (1.0f + __expf(-zp));
        float sp = hp;
        sp += __shfl_xor_sync(0xffffffffu, sp, 1);
        sp += __shfl_xor_sync(0xffffffffu, sp, 2);
        s_hpre[tt * 4 + r] = hp / (sp + EPS_W);

        float zq = fmaf(a_post, inv * dt[4 + r], bpost[r]);
        float hq = 2.0f / (1.0f + __expf(-zq));
        float sq = hq;
        sq += __shfl_xor_sync(0xffffffffu, sq, 1);
        sq += __shfl_xor_sync(0xffffffffu, sq, 2);
        g_Hpost[t * NS + r] = hq / (sq + EPS_W);

        float Zrow[4], Zcol[4];
        #pragma unroll
        for (int i = 0; i < 4; i++) {
            Zrow[i] = fmaf(a_res, inv * dt[8 + r * 4 + i], bres[r * 4 + i]) * TAU_INV;
            Zcol[i] = fmaf(a_res, inv * dt[8 + i * 4 + r], bres[i * 4 + r]) * TAU_INV;
        }
        float ur = 0.f, vr = 0.f;
        for (int it = 0; it < 20; it++) {
            float v0 = __shfl_sync(0xffffffffu, vr, base + 0);
            float v1 = __shfl_sync(0xffffffffu, vr, base + 1);
            float v2 = __shfl_sync(0xffffffffu, vr, base + 2);
            float v3 = __shfl_sync(0xffffffffu, vr, base + 3);
            ur = -lse4(Zrow[0] + v0, Zrow[1] + v1, Zrow[2] + v2, Zrow[3] + v3);
            float u0 = __shfl_sync(0xffffffffu, ur, base + 0);
            float u1 = __shfl_sync(0xffffffffu, ur, base + 1);
            float u2 = __shfl_sync(0xffffffffu, ur, base + 2);
            float u3 = __shfl_sync(0xffffffffu, ur, base + 3);
            vr = -lse4(Zcol[0] + u0, Zcol[1] + u1, Zcol[2] + u2, Zcol[3] + u3);
        }
        float v0 = __shfl_sync(0xffffffffu, vr, base + 0);
        float v1 = __shfl_sync(0xffffffffu, vr, base + 1);
        float v2 = __shfl_sync(0xffffffffu, vr, base + 2);
        float v3 = __shfl_sync(0xffffffffu, vr, base + 3);
        g_Hres[t * 16 + r * 4 + 0] = __expf(Zrow[0] + ur + v0);
        g_Hres[t * 16 + r * 4 + 1] = __expf(Zrow[1] + ur + v1);
        g_Hres[t * 16 + r * 4 + 2] = __expf(Zrow[2] + ur + v2);
        g_Hres[t * 16 + r * 4 + 3] = __expf(Zrow[3] + ur + v3);
    }
    __syncthreads();

    // ---- pass 3: x_layer -> fp16 (single term) ----
    #pragma unroll 4
    for (int gg = 0; gg < TOKB; gg++) {
        const long t = t0 + gg;
        const float h0 = s_hpre[gg * 4 + 0], h1 = s_hpre[gg * 4 + 1];
        const float h2 = s_hpre[gg * 4 + 2], h3 = s_hpre[gg * 4 + 3];
        const float4* xr = (const float4*)(x + t * D);
        float4 a = xr[tid], b = xr[256 + tid], c = xr[512 + tid], e = xr[768 + tid];
        float4 o;
        o.x = h0 * a.x + h1 * b.x + h2 * c.x + h3 * e.x;
        o.y = h0 * a.y + h1 * b.y + h2 * c.y + h3 * e.y;
        o.z = h0 * a.z + h1 * b.z + h2 * c.z + h3 * e.z;
        o.w = h0 * a.w + h1 * b.w + h2 * c.w + h3 * e.w;
        uint2 hv;
        hv.x = packh2(__float2half_rn(o.x), __float2half_rn(o.y));
        hv.y = packh2(__float2half_rn(o.z), __float2half_rn(o.w));
        ((uint2*)g_xhi)[t * 256 + tid] = hv;
    }
}

// ============================================================
// Kernel 2: fp16 1-term GEMM (mma.sync) + fused mix epilogue
//   CTA 128x128, 8 warps, GK=32/stage (16KB), 4 stages, 2 CTAs/SM.
// ============================================================
#define GM 128
#define GN 128
#define GK 32
#define ST_A 0
#define ST_B 8192
#define STAGE_BYTES 16384
#define NSTAGE 4
#define EP_YS   0
#define EP_HRES 69632
#define EP_HPST 77824
#define GEMM_SMEM 79872

__device__ __forceinline__ void load_stage(
    uint32_t sstage, int tid, int m0, int n0, int k0,
    const __half* __restrict__ Ah, const __half* __restrict__ Bh)
{
    #pragma unroll
    for (int j = 0; j < 4; j++) {
        int i = tid + (j << 8);
        int mat = i >> 9;
        int w = i & 511;
        int r = w >> 2, c = w & 3;
        uint32_t so = SW64((uint32_t)(r * 64 + c * 16));
        const __half* src = (mat == 0) ? Ah : Bh;
        size_t go = (mat == 0) ? ((size_t)(m0 + r) * HID + k0 + c * 8)
                               : ((size_t)(n0 + r) * HID + k0 + c * 8);
        cp16(sstage + mat * 8192 + so, src + go);
    }
}

__global__ __launch_bounds__(256, 2)
void gemm_tc_kernel(const __half* __restrict__ Ah,
                    const __half* __restrict__ Bh,
                    const float* __restrict__ x,
                    float* __restrict__ out)
{
    extern __shared__ __align__(16) char smem[];
    uint32_t sbase = smem_to_u32(smem);
    const int tid = threadIdx.x, wid = tid >> 5, lane = tid & 31;
    const int wm = wid & 3, wn = wid >> 2;
    const int m0 = blockIdx.y * GM, n0 = blockIdx.x * GN;

    float acc[2][8][4];
    #pragma unroll
    for (int h = 0; h < 2; h++)
        #pragma unroll
        for (int g = 0; g < 8; g++)
            #pragma unroll
            for (int q = 0; q < 4; q++) acc[h][g][q] = 0.f;

    const int a_row = (lane & 15);
    const int a_kx  = ((lane >> 4) & 1) * 16;
    const int b_row = (lane & 7) + ((lane >> 4) & 1) * 8;
    const int b_kx  = ((lane >> 3) & 1) * 16;

    #pragma unroll
    for (int p = 0; p < 3; p++) {
        load_stage(sbase + p * STAGE_BYTES, tid, m0, n0, p * GK, Ah, Bh);
        asm volatile("cp.async.commit_group;" ::: "memory");
    }

    const int NITER = HID / GK;   // 32
    for (int i = 0; i < NITER; i++) {
        if (i + 2 < NITER)      asm volatile("cp.async.wait_group 2;" ::: "memory");
        else if (i + 1 < NITER) asm volatile("cp.async.wait_group 1;" ::: "memory");
        else                    asm volatile("cp.async.wait_group 0;" ::: "memory");
        __syncthreads();
        if (i + 3 < NITER) {
            load_stage(sbase + ((i + 3) % NSTAGE) * STAGE_BYTES, tid, m0, n0,
                       (i + 3) * GK, Ah, Bh);
            asm volatile("cp.async.commit_group;" ::: "memory");
        }

        uint32_t stg = sbase + (i % NSTAGE) * STAGE_BYTES;
        #pragma unroll
        for (int kk = 0; kk < 2; kk++) {
            const int kb = kk * 32;
            uint32_t ah[2][4];
            #pragma unroll
            for (int h = 0; h < 2; h++) {
                uint32_t off = SW64((uint32_t)((32 * wm + 16 * h + a_row) * 64 + kb + a_kx));
                ldsm_x4(ah[h][0], ah[h][1], ah[h][2], ah[h][3], stg + ST_A + off);
            }
            #pragma unroll
            for (int g = 0; g < 4; g++) {
                uint32_t bh[4];
                uint32_t off = SW64((uint32_t)((64 * wn + 16 * g + b_row) * 64 + kb + b_kx));
                ldsm_x4(bh[0], bh[1], bh[2], bh[3], stg + ST_B + off);
                #pragma unroll
                for (int half = 0; half < 2; half++)
                    #pragma unroll
                    for (int h = 0; h < 2; h++)
                        mma16816h(acc[h][g * 2 + half], ah[h], &bh[2 * half]);
            }
        }
    }

    // ================== fused mix epilogue ==================
    __syncthreads();
    float* ys  = (float*)(smem + EP_YS);   // [128][132]
    float* shr = (float*)(smem + EP_HRES); // [128][16]
    float* shp = (float*)(smem + EP_HPST); // [128][4]

    {
        const int r0 = 32 * wm + (lane >> 2);
        const int c0 = 64 * wn + (lane & 3) * 2;
        #pragma unroll
        for (int h = 0; h < 2; h++)
            #pragma unroll
            for (int ng = 0; ng < 8; ng++) {
                int rr = r0 + 16 * h, cc = c0 + 8 * ng;
                *(float2*)&ys[rr * 132 + cc]       = make_float2(acc[h][ng][0], acc[h][ng][1]);
                *(float2*)&ys[(rr + 8) * 132 + cc] = make_float2(acc[h][ng][2], acc[h][ng][3]);
            }
    }
    #pragma unroll
    for (int j = 0; j < 8; j++) shr[tid + j * 256] = g_Hres[(size_t)m0 * 16 + tid + j * 256];
    #pragma unroll
    for (int j = 0; j < 2; j++) shp[tid + j * 256] = g_Hpost[(size_t)m0 * 4 + tid + j * 256];
    __syncthreads();

    const int col4 = lane;
    #pragma unroll 2
    for (int it = 0; it < 16; it++) {
        const int trow = wid + 8 * it;
        const size_t t = (size_t)(m0 + trow);
        const float* hr = shr + trow * 16;
        const float p0 = shp[trow * 4 + 0], p1 = shp[trow * 4 + 1];
        const float p2 = shp[trow * 4 + 2], p3 = shp[trow * 4 + 3];
        float4 y4 = *(const float4*)&ys[trow * 132 + col4 * 4];
        const float* xb = x + t * D + n0 + col4 * 4;
        float4 xi0 = *(const float4*)(xb);
        float4 xi1 = *(const float4*)(xb + 1024);
        float4 xi2 = *(const float4*)(xb + 2048);
        float4 xi3 = *(const float4*)(xb + 3072);
        float* ob = out + t * D + n0 + col4 * 4;
        #pragma unroll
        for (int o = 0; o < 4; o++) {
            const float h0 = hr[o * 4 + 0], h1 = hr[o * 4 + 1];
            const float h2 = hr[o * 4 + 2], h3 = hr[o * 4 + 3];
            const float p = (o == 0) ? p0 : (o == 1) ? p1 : (o == 2) ? p2 : p3;
            float4 r;
            r.x = h0 * xi0.x + h1 * xi1.x + h2 * xi2.x + h3 * xi3.x + p * y4.x;
            r.y = h0 * xi0.y + h1 * xi1.y + h2 * xi2.y + h3 * xi3.y + p * y4.y;
            r.z = h0 * xi0.z + h1 * xi1.z + h2 * xi2.z + h3 * xi3.z + p * y4.z;
            r.w = h0 * xi0.w + h1 * xi1.w + h2 * xi2.w + h3 * xi3.w + p * y4.w;
            *(float4*)(ob + o * 1024) = r;
        }
    }
}

// ============================================================
extern "C" void kernel_launch(void* const* d_in, const int* in_sizes, int n_in,
                              void* d_out, int out_size)
{
    const float* x      = (const float*)d_in[0];
    const float* rmsw   = (const float*)d_in[1];
    const float* Wpre   = (const float*)d_in[2];
    const float* Wpost  = (const float*)d_in[3];
    const float* Wres   = (const float*)d_in[4];
    const float* bpre   = (const float*)d_in[5];
    const float* bpost  = (const float*)d_in[6];
    const float* bres   = (const float*)d_in[7];
    const float* apre   = (const float*)d_in[8];
    const float* apost  = (const float*)d_in[9];
    const float* ares   = (const float*)d_in[10];
    const float* Wsub   = (const float*)d_in[11];
    float* out = (float*)d_out;

    __half *xhi_p, *wh_p;
    cudaGetSymbolAddress((void**)&xhi_p, g_xhi);
    cudaGetSymbolAddress((void**)&wh_p, g_wh);

    cudaFuncSetAttribute(gemm_tc_kernel,
                         cudaFuncAttributeMaxDynamicSharedMemorySize, GEMM_SMEM);
    cudaFuncSetAttribute(gates_kernel,
                         cudaFuncAttributeMaxDynamicSharedMemorySize, GATES_SMEM);

    prep_kernel<<<384 + HID * HID / 4 / 256, 256>>>(Wpre, Wpost, Wres, rmsw, Wsub);
    gates_kernel<<<T_TOKENS / TOKB, 256, GATES_SMEM>>>(x, bpre, bpost, bres,
                                                       apre, apost, ares);
    gemm_tc_kernel<<<dim3(HID / GN, T_TOKENS / GM), 256, GEMM_SMEM>>>(
        xhi_p, wh_p, x, out);
}